// round 10
// baseline (speedup 1.0000x reference)
#include <cuda_runtime.h>
#include <cstdint>

#define B_  8
#define S_  1024
#define H_  1024
#define NH  16
#define HD  64
#define M_  (B_ * S_)   // 8192

__device__ float g_q[B_ * NH * S_ * HD];
__device__ float g_k[B_ * NH * S_ * HD];
__device__ float g_v[B_ * NH * S_ * HD];

__device__ __forceinline__ uint32_t f2tf(float x) {
    uint32_t r;
    asm("cvt.rna.tf32.f32 %0, %1;" : "=r"(r) : "f"(x));
    return r;
}

__device__ __forceinline__ void mma_tf32(float c[4],
                                         uint32_t a0, uint32_t a1, uint32_t a2, uint32_t a3,
                                         uint32_t b0, uint32_t b1) {
    asm volatile(
        "mma.sync.aligned.m16n8k8.row.col.f32.tf32.tf32.f32 "
        "{%0,%1,%2,%3}, {%4,%5,%6,%7}, {%8,%9}, {%0,%1,%2,%3};\n"
        : "+f"(c[0]), "+f"(c[1]), "+f"(c[2]), "+f"(c[3])
        : "r"(a0), "r"(a1), "r"(a2), "r"(a3), "r"(b0), "r"(b1));
}

// ---------------------------------------------------------------------------
// TF32 QKV GEMM (unchanged — measured, unprofiled; no blind edits).
// ---------------------------------------------------------------------------
#define GP 24

__global__ __launch_bounds__(256) void qkv_gemm_tf32(
    const float* __restrict__ X,
    const float* __restrict__ Wq, const float* __restrict__ Bq,
    const float* __restrict__ Wk, const float* __restrict__ Bk,
    const float* __restrict__ Wv, const float* __restrict__ Bv)
{
    const int which = blockIdx.z;
    const float* W    = (which == 0) ? Wq : (which == 1 ? Wk : Wv);
    const float* bias = (which == 0) ? Bq : (which == 1 ? Bk : Bv);
    float* out        = (which == 0) ? g_q : (which == 1 ? g_k : g_v);

    __shared__ uint32_t sA[2][128 * GP];
    __shared__ uint32_t sB[2][128 * GP];

    const int tid  = threadIdx.x;
    const int lane = tid & 31;
    const int wid  = tid >> 5;
    const int wm   = (wid >> 1) * 32;
    const int wn   = (wid & 1) * 64;
    const int m0   = blockIdx.y * 128;
    const int n0   = blockIdx.x * 128;
    const int r8   = lane >> 2;
    const int la3  = lane & 3;

    const int lrow = tid >> 1;
    const int lcol = (tid & 1) * 8;

    const float* pA = X + (size_t)(m0 + lrow) * H_ + lcol;
    const float* pB = W + (size_t)(n0 + lrow) * H_ + lcol;
    uint32_t* stA = &sA[0][0] + lrow * GP + lcol;
    uint32_t* stB = &sB[0][0] + lrow * GP + lcol;

    float c[2][8][4];
    #pragma unroll
    for (int i = 0; i < 2; i++)
        #pragma unroll
        for (int j = 0; j < 8; j++)
            #pragma unroll
            for (int k = 0; k < 4; k++) c[i][j][k] = 0.0f;

    float4 alo = *(const float4*)(pA);
    float4 ahi = *(const float4*)(pA + 4);
    float4 blo = *(const float4*)(pB);
    float4 bhi = *(const float4*)(pB + 4);
    {
        *(uint2*)(stA + 0) = make_uint2(f2tf(alo.x), f2tf(ahi.x));
        *(uint2*)(stA + 2) = make_uint2(f2tf(alo.y), f2tf(ahi.y));
        *(uint2*)(stA + 4) = make_uint2(f2tf(alo.z), f2tf(ahi.z));
        *(uint2*)(stA + 6) = make_uint2(f2tf(alo.w), f2tf(ahi.w));
        *(uint2*)(stB + 0) = make_uint2(f2tf(blo.x), f2tf(bhi.x));
        *(uint2*)(stB + 2) = make_uint2(f2tf(blo.y), f2tf(bhi.y));
        *(uint2*)(stB + 4) = make_uint2(f2tf(blo.z), f2tf(bhi.z));
        *(uint2*)(stB + 6) = make_uint2(f2tf(blo.w), f2tf(bhi.w));
    }
    __syncthreads();

    const int NT = H_ / 16;
    for (int t = 0; t < NT; t++) {
        const int cur = t & 1;
        if (t + 1 < NT) {
            const float* nA = pA + (t + 1) * 16;
            const float* nB = pB + (t + 1) * 16;
            alo = *(const float4*)(nA);
            ahi = *(const float4*)(nA + 4);
            blo = *(const float4*)(nB);
            bhi = *(const float4*)(nB + 4);
        }

        const uint32_t* cA = &sA[cur][0];
        const uint32_t* cB = &sB[cur][0];
        #pragma unroll
        for (int g = 0; g < 2; g++) {
            uint2 uA0[2], uA1[2];
            #pragma unroll
            for (int mi = 0; mi < 2; mi++) {
                uA0[mi] = *(const uint2*)&cA[(wm + mi * 16 + r8) * GP + g * 8 + la3 * 2];
                uA1[mi] = *(const uint2*)&cA[(wm + mi * 16 + 8 + r8) * GP + g * 8 + la3 * 2];
            }
            #pragma unroll
            for (int ni = 0; ni < 8; ni++) {
                uint2 uB = *(const uint2*)&cB[(wn + ni * 8 + r8) * GP + g * 8 + la3 * 2];
                #pragma unroll
                for (int mi = 0; mi < 2; mi++)
                    mma_tf32(c[mi][ni], uA0[mi].x, uA1[mi].x, uA0[mi].y, uA1[mi].y,
                             uB.x, uB.y);
            }
        }

        if (t + 1 < NT) {
            uint32_t* dA = stA + ((t + 1) & 1) * 128 * GP;
            uint32_t* dB = stB + ((t + 1) & 1) * 128 * GP;
            *(uint2*)(dA + 0) = make_uint2(f2tf(alo.x), f2tf(ahi.x));
            *(uint2*)(dA + 2) = make_uint2(f2tf(alo.y), f2tf(ahi.y));
            *(uint2*)(dA + 4) = make_uint2(f2tf(alo.z), f2tf(ahi.z));
            *(uint2*)(dA + 6) = make_uint2(f2tf(alo.w), f2tf(ahi.w));
            *(uint2*)(dB + 0) = make_uint2(f2tf(blo.x), f2tf(bhi.x));
            *(uint2*)(dB + 2) = make_uint2(f2tf(blo.y), f2tf(bhi.y));
            *(uint2*)(dB + 4) = make_uint2(f2tf(blo.z), f2tf(bhi.z));
            *(uint2*)(dB + 6) = make_uint2(f2tf(blo.w), f2tf(bhi.w));
        }
        __syncthreads();
    }

    #pragma unroll
    for (int mi = 0; mi < 2; mi++) {
        #pragma unroll
        for (int rh = 0; rh < 2; rh++) {
            const int m = m0 + wm + mi * 16 + r8 + rh * 8;
            const int b = m >> 10;
            const int s = m & 1023;
            float* orow = out + ((size_t)(b * NH) * S_ + s) * HD;
            #pragma unroll
            for (int ni = 0; ni < 8; ni++) {
                const int n = n0 + wn + ni * 8 + la3 * 2;
                const int h = n >> 6;
                const int dd = n & 63;
                float2 v;
                v.x = c[mi][ni][rh * 2 + 0] + bias[n];
                v.y = c[mi][ni][rh * 2 + 1] + bias[n + 1];
                *(float2*)(orow + (size_t)h * S_ * HD + dd) = v;
            }
        }
    }
}

// ---------------------------------------------------------------------------
// TF32 flash attention, P-direct + 3 CTAs/SM.
// Q pre-scaled by 0.125*log2(e) -> exp2f softmax (no ln2 multiplies).
// Q fragments re-loaded from sQP per k-group (hoist dropped to fit 84 regs).
// smem 73728 B/CTA -> 3 CTAs = 216 KB/SM.
// ---------------------------------------------------------------------------
#define AP 72
#define QSCALE 0.18033688f   // 0.125 * log2(e)

__global__ __launch_bounds__(256, 3) void attn_tf32(float* __restrict__ out)
{
    extern __shared__ uint32_t sm[];
    uint32_t* sQP = sm;                       // Q (q, d-interleaved) [128][AP]
    uint32_t* sK  = sQP + 128 * AP;           // [64][AP] (kv, d-interleaved)
    uint32_t* sVt = sK + 64 * AP;             // [64][AP] (d, kv-perm-interleaved)

    const int tid  = threadIdx.x;
    const int lane = tid & 31;
    const int wid  = tid >> 5;
    const int wq   = wid * 16;
    const int r8   = lane >> 2;
    const int la3  = lane & 3;
    const int bh   = blockIdx.y;
    const int qt   = blockIdx.x;

    const float* Q = g_q + (size_t)bh * S_ * HD + (size_t)qt * 128 * HD;
    const float* K = g_k + (size_t)bh * S_ * HD;
    const float* V = g_v + (size_t)bh * S_ * HD;

    // Stage Q (scaled by 0.125*log2e, tf32, interleaved)
    {
        const int r  = tid >> 1;
        const int c0 = (tid & 1) * 32;
        #pragma unroll
        for (int jj = 0; jj < 4; jj++) {
            const int cc = c0 + jj * 8;
            float4 lo = *(const float4*)&Q[r * HD + cc];
            float4 hi = *(const float4*)&Q[r * HD + cc + 4];
            uint32_t* dst = &sQP[r * AP + cc];
            *(uint2*)(dst + 0) = make_uint2(f2tf(lo.x * QSCALE), f2tf(hi.x * QSCALE));
            *(uint2*)(dst + 2) = make_uint2(f2tf(lo.y * QSCALE), f2tf(hi.y * QSCALE));
            *(uint2*)(dst + 4) = make_uint2(f2tf(lo.z * QSCALE), f2tf(hi.z * QSCALE));
            *(uint2*)(dst + 6) = make_uint2(f2tf(lo.w * QSCALE), f2tf(hi.w * QSCALE));
        }
    }
    __syncthreads();

    float o[8][4];
    #pragma unroll
    for (int i = 0; i < 8; i++)
        #pragma unroll
        for (int j = 0; j < 4; j++) o[i][j] = 0.0f;
    float mr0 = -1e30f, mr1 = -1e30f;   // log2-domain row maxes
    float lr0 = 0.0f,   lr1 = 0.0f;

    for (int t = 0; t < 16; t++) {
        __syncthreads();   // all warps done with sK/sVt

        // Load K (interleaved) + V (transposed, kv-permuted-interleaved)
        {
            const int rr  = tid >> 2;          // 0..63
            const int c0  = (tid & 3) * 16;
            const int ipr = (rr >> 3) * 8 + ((rr >> 1) & 3) * 2 + (rr & 1);
            const float* Kt = K + (size_t)t * 64 * HD;
            const float* Vt = V + (size_t)t * 64 * HD;
            #pragma unroll
            for (int jj = 0; jj < 2; jj++) {
                const int cc = c0 + jj * 8;
                float4 lo = *(const float4*)&Kt[rr * HD + cc];
                float4 hi = *(const float4*)&Kt[rr * HD + cc + 4];
                uint32_t* dst = &sK[rr * AP + cc];
                *(uint2*)(dst + 0) = make_uint2(f2tf(lo.x), f2tf(hi.x));
                *(uint2*)(dst + 2) = make_uint2(f2tf(lo.y), f2tf(hi.y));
                *(uint2*)(dst + 4) = make_uint2(f2tf(lo.z), f2tf(hi.z));
                *(uint2*)(dst + 6) = make_uint2(f2tf(lo.w), f2tf(hi.w));
            }
            #pragma unroll
            for (int jj = 0; jj < 4; jj++) {
                const int cc = c0 + jj * 4;
                float4 v4 = *(const float4*)&Vt[rr * HD + cc];
                sVt[(cc + 0) * AP + ipr] = f2tf(v4.x);
                sVt[(cc + 1) * AP + ipr] = f2tf(v4.y);
                sVt[(cc + 2) * AP + ipr] = f2tf(v4.z);
                sVt[(cc + 3) * AP + ipr] = f2tf(v4.w);
            }
        }
        __syncthreads();

        // S = Q @ K^T (Q fragments from smem per k-group)
        float s[8][4];
        #pragma unroll
        for (int i = 0; i < 8; i++)
            #pragma unroll
            for (int j = 0; j < 4; j++) s[i][j] = 0.0f;

        #pragma unroll
        for (int g = 0; g < 8; g++) {
            uint2 qa = *(const uint2*)&sQP[(wq + r8) * AP + g * 8 + la3 * 2];
            uint2 qb = *(const uint2*)&sQP[(wq + 8 + r8) * AP + g * 8 + la3 * 2];
            #pragma unroll
            for (int ni = 0; ni < 8; ni++) {
                uint2 b = *(const uint2*)&sK[(ni * 8 + r8) * AP + g * 8 + la3 * 2];
                mma_tf32(s[ni], qa.x, qb.x, qa.y, qb.y, b.x, b.y);
            }
        }

        // Online softmax in log2 domain (exp2f; no ln2 multiplies)
        {
            float rm0 = -1e30f, rm1 = -1e30f;
            #pragma unroll
            for (int ni = 0; ni < 8; ni++) {
                rm0 = fmaxf(rm0, fmaxf(s[ni][0], s[ni][1]));
                rm1 = fmaxf(rm1, fmaxf(s[ni][2], s[ni][3]));
            }
            rm0 = fmaxf(rm0, __shfl_xor_sync(0xffffffffu, rm0, 1));
            rm0 = fmaxf(rm0, __shfl_xor_sync(0xffffffffu, rm0, 2));
            rm1 = fmaxf(rm1, __shfl_xor_sync(0xffffffffu, rm1, 1));
            rm1 = fmaxf(rm1, __shfl_xor_sync(0xffffffffu, rm1, 2));

            const float mn0 = fmaxf(mr0, rm0);
            const float mn1 = fmaxf(mr1, rm1);
            const float cor0 = exp2f(mr0 - mn0);
            const float cor1 = exp2f(mr1 - mn1);
            mr0 = mn0; mr1 = mn1;

            float rs0 = 0.0f, rs1 = 0.0f;
            #pragma unroll
            for (int ni = 0; ni < 8; ni++) {
                s[ni][0] = exp2f(s[ni][0] - mn0);
                s[ni][1] = exp2f(s[ni][1] - mn0);
                s[ni][2] = exp2f(s[ni][2] - mn1);
                s[ni][3] = exp2f(s[ni][3] - mn1);
                rs0 += s[ni][0] + s[ni][1];
                rs1 += s[ni][2] + s[ni][3];
            }
            rs0 += __shfl_xor_sync(0xffffffffu, rs0, 1);
            rs0 += __shfl_xor_sync(0xffffffffu, rs0, 2);
            rs1 += __shfl_xor_sync(0xffffffffu, rs1, 1);
            rs1 += __shfl_xor_sync(0xffffffffu, rs1, 2);
            lr0 = lr0 * cor0 + rs0;
            lr1 = lr1 * cor1 + rs1;

            #pragma unroll
            for (int ni = 0; ni < 8; ni++) {
                o[ni][0] *= cor0; o[ni][1] *= cor0;
                o[ni][2] *= cor1; o[ni][3] *= cor1;
            }
        }

        // O += P @ V — P consumed directly from S accumulators
        #pragma unroll
        for (int g = 0; g < 8; g++) {
            const uint32_t pa0 = f2tf(s[g][0]);
            const uint32_t pa1 = f2tf(s[g][2]);
            const uint32_t pa2 = f2tf(s[g][1]);
            const uint32_t pa3 = f2tf(s[g][3]);
            #pragma unroll
            for (int ni = 0; ni < 8; ni++) {
                uint2 b = *(const uint2*)&sVt[(ni * 8 + r8) * AP + g * 8 + la3 * 2];
                mma_tf32(o[ni], pa0, pa1, pa2, pa3, b.x, b.y);
            }
        }
    }

    // Epilogue: normalize, write [B, S, H]
    const int b = bh >> 4;
    const int h = bh & 15;
    const float inv0 = 1.0f / lr0;
    const float inv1 = 1.0f / lr1;
    const int s0 = qt * 128 + wq + r8;
    float* out0 = out + ((size_t)(b * S_ + s0)) * H_ + h * HD;
    float* out1 = out + ((size_t)(b * S_ + s0 + 8)) * H_ + h * HD;
    #pragma unroll
    for (int ni = 0; ni < 8; ni++) {
        const int dd = ni * 8 + la3 * 2;
        float2 v0 = {o[ni][0] * inv0, o[ni][1] * inv0};
        float2 v1 = {o[ni][2] * inv1, o[ni][3] * inv1};
        *(float2*)(out0 + dd) = v0;
        *(float2*)(out1 + dd) = v1;
    }
}

extern "C" void kernel_launch(void* const* d_in, const int* in_sizes, int n_in,
                              void* d_out, int out_size)
{
    const float* X  = (const float*)d_in[0];
    const float* Wq = (const float*)d_in[1];
    const float* Bq = (const float*)d_in[2];
    const float* Wk = (const float*)d_in[3];
    const float* Bk = (const float*)d_in[4];
    const float* Wv = (const float*)d_in[5];
    const float* Bv = (const float*)d_in[6];
    float* out = (float*)d_out;

    dim3 g1(H_ / 128, M_ / 128, 3);     // (8, 64, 3)
    qkv_gemm_tf32<<<g1, 256>>>(X, Wq, Bq, Wk, Bk, Wv, Bv);

    const int smem_attn = (128 + 64 + 64) * AP * 4;   // 73728 B
    cudaFuncSetAttribute(attn_tf32, cudaFuncAttributeMaxDynamicSharedMemorySize, smem_attn);
    dim3 g2(S_ / 128, B_ * NH);         // (8, 128)
    attn_tf32<<<g2, 256, smem_attn>>>(out);
}